// round 4
// baseline (speedup 1.0000x reference)
#include <cuda_runtime.h>
#include <cuda_bf16.h>
#include <cstdint>

// ---------------- problem constants ----------------
#define BATCH 8192
#define NNODE 30
#define FEAT  256
#define MROWS (BATCH * NNODE)

// ---------------- weights scratch (device globals) ----------------
__device__ __nv_bfloat16 g_w1h[FEAT * FEAT], g_w1l[FEAT * FEAT];
__device__ __nv_bfloat16 g_w2h[FEAT * FEAT], g_w2l[FEAT * FEAT];

// ==================== helpers ====================
__device__ __forceinline__ uint32_t smem_to_u32(const void* p) {
    uint32_t a;
    asm("{ .reg .u64 t; cvta.to.shared.u64 t, %1; cvt.u32.u64 %0, t; }" : "=r"(a) : "l"(p));
    return a;
}
__device__ __forceinline__ void cpasync16(uint32_t saddr, const void* g) {
    asm volatile("cp.async.cg.shared.global [%0], [%1], 16;" :: "r"(saddr), "l"(g));
}
__device__ __forceinline__ void ldsm4(uint32_t* r, uint32_t addr) {
    asm volatile("ldmatrix.sync.aligned.m8n8.x4.shared.b16 {%0,%1,%2,%3}, [%4];"
        : "=r"(r[0]), "=r"(r[1]), "=r"(r[2]), "=r"(r[3]) : "r"(addr));
}
__device__ __forceinline__ void mma_bf16(float* d, const uint32_t* a, uint32_t b0, uint32_t b1) {
    asm volatile(
        "mma.sync.aligned.m16n8k16.row.col.f32.bf16.bf16.f32 "
        "{%0,%1,%2,%3}, {%4,%5,%6,%7}, {%8,%9}, {%0,%1,%2,%3};"
        : "+f"(d[0]), "+f"(d[1]), "+f"(d[2]), "+f"(d[3])
        : "r"(a[0]), "r"(a[1]), "r"(a[2]), "r"(a[3]), "r"(b0), "r"(b1));
}

// =====================================================================
// prep_w: transpose W1/W2 to [N,K] K-major, split into bf16 hi/lo
// =====================================================================
__global__ void prep_w(const float* __restrict__ W1, const float* __restrict__ W2,
                       __nv_bfloat16* __restrict__ w1h, __nv_bfloat16* __restrict__ w1l,
                       __nv_bfloat16* __restrict__ w2h, __nv_bfloat16* __restrict__ w2l) {
    const int n = blockIdx.x, k = threadIdx.x;
    float v1 = W1[k * 256 + n];
    __nv_bfloat16 h1 = __float2bfloat16_rn(v1);
    w1h[n * 256 + k] = h1;
    w1l[n * 256 + k] = __float2bfloat16_rn(v1 - __bfloat162float(h1));
    float v2 = W2[k * 256 + n];
    __nv_bfloat16 h2 = __float2bfloat16_rn(v2);
    w2h[n * 256 + k] = h2;
    w2l[n * 256 + k] = __float2bfloat16_rn(v2 - __bfloat162float(h2));
}

// =====================================================================
// MEGA kernel: 4 batches (120 rows, padded to 128) per CTA, 256 threads.
// smem layout:
//   RA   [0,       131072): A region. Phases: y1split -> h1split -> u2(fp32)
//        split layout: hi = 4 chunks of [128 x 64]bf16 (16KB, SW128-swizzled)
//                      lo = same at +65536
//   RW   [131072,  196608): W stages (2 x 32KB: hi 16KB + lo 16KB, KC=32)
//                           (phase A: x stages 2 x 30720B)
//   ADJ  [196608,  211968): adj 4 x [30 x 32] fp32
//   B1   [211968,  212992): bias1 256 fp32
//   RED  [212992,  213952): reduction scratch 4*30*2 fp32
// =====================================================================
#define SM_RA   0u
#define SM_RW   131072u
#define SM_ADJ  196608u
#define SM_B1   211968u
#define SM_RED  212992u
#define SMEM_TOTAL 214016

__global__ __launch_bounds__(256, 1)
void mega(const float* __restrict__ x, const float* __restrict__ graph,
          const float* __restrict__ b1g, const float* __restrict__ b2g,
          const float* __restrict__ wling, const float* __restrict__ bling,
          const float* __restrict__ Wheadg, const float* __restrict__ bheadg,
          const __nv_bfloat16* __restrict__ W1h, const __nv_bfloat16* __restrict__ W1l,
          const __nv_bfloat16* __restrict__ W2h, const __nv_bfloat16* __restrict__ W2l,
          float* __restrict__ out) {
    extern __shared__ char smem[];
    const uint32_t sb = smem_to_u32(smem);
    const int tid = threadIdx.x, lane = tid & 31, wid = tid >> 5;
    const int warp_m = wid & 3, warp_n = wid >> 2;
    const size_t b0 = (size_t)blockIdx.x * 4;
    float* adj_s = (float*)(smem + SM_ADJ);

    // ---------------- adj = mean(graph, bands) ----------------
    for (int e = tid; e < 3600; e += 256) {
        int b = e / 900, i = e - b * 900;
        const float* gp = graph + (b0 + b) * 4500 + i;
        float s = 0.2f * (gp[0] + gp[900] + gp[1800] + gp[2700] + gp[3600]);
        adj_s[b * 960 + (i / 30) * 32 + (i % 30)] = s;
    }
    ((float*)(smem + SM_B1))[tid] = b1g[tid];

    // ---------------- Phase A: y1 = adj @ x -> bf16 split ----------------
    auto xload = [&](int c) {
        const float* gx = x + (b0 * 30) * 256 + c * 64;
        uint32_t st = sb + SM_RW + (uint32_t)(c & 1) * 30720u;
        #pragma unroll
        for (int u = tid; u < 1920; u += 256) {
            int row = u >> 4, seg = u & 15;
            cpasync16(st + (uint32_t)(row * 256 + seg * 16), gx + (size_t)row * 256 + seg * 4);
        }
        asm volatile("cp.async.commit_group;" ::: "memory");
    };
    xload(0);
    xload(1);

    const int pb = tid >> 6, phalf = (tid >> 5) & 1, pcp = tid & 31;
    __syncthreads();   // adj + b1 visible

    #pragma unroll 1
    for (int c = 0; c < 4; ++c) {
        if (c < 3) asm volatile("cp.async.wait_group 1;" ::: "memory");
        else       asm volatile("cp.async.wait_group 0;" ::: "memory");
        __syncthreads();
        const float* xs = (const float*)(smem + SM_RW + (c & 1) * 30720);
        float2 xk[30];
        #pragma unroll
        for (int k = 0; k < 30; ++k)
            xk[k] = *(const float2*)(xs + (pb * 30 + k) * 64 + pcp * 2);
        const float* ar = adj_s + pb * 960 + phalf * 15 * 32;
        #pragma unroll 1
        for (int i = 0; i < 15; ++i) {
            float s0 = 0.f, s1 = 0.f;
            #pragma unroll
            for (int k = 0; k < 30; ++k) {
                float a = ar[i * 32 + k];
                s0 = fmaf(a, xk[k].x, s0);
                s1 = fmaf(a, xk[k].y, s1);
            }
            int r = pb * 30 + phalf * 15 + i;
            __nv_bfloat16 h0 = __float2bfloat16_rn(s0), h1 = __float2bfloat16_rn(s1);
            __nv_bfloat162 hv; hv.x = h0; hv.y = h1;
            __nv_bfloat162 lv;
            lv.x = __float2bfloat16_rn(s0 - __bfloat162float(h0));
            lv.y = __float2bfloat16_rn(s1 - __bfloat162float(h1));
            uint32_t B = (uint32_t)(pcp * 4);
            uint32_t off = (uint32_t)c * 16384u + (uint32_t)(r * 128)
                         + (B ^ ((uint32_t)(r & 7) << 4));
            *(__nv_bfloat162*)(smem + SM_RA + off)           = hv;
            *(__nv_bfloat162*)(smem + SM_RA + 65536u + off)  = lv;
        }
        // zero pad rows 120..127 (hi and lo)
        if (tid < 128) {
            int hl = tid >> 6, rr = 120 + ((tid >> 3) & 7), seg = tid & 7;
            uint32_t off = (uint32_t)c * 16384u + (uint32_t)(rr * 128 + seg * 16)
                         + (uint32_t)hl * 65536u;
            *(uint4*)(smem + SM_RA + off) = make_uint4(0, 0, 0, 0);
        }
        __syncthreads();
        if (c + 2 < 4) xload(c + 2);
    }

    // ---------------- GEMM machinery ----------------
    float acc[2][16][4];
    const int matv = lane >> 3;
    const int rA0 = warp_m * 32 + (matv & 1) * 8 + (lane & 7);
    const int kAoff = (matv >> 1) * 16;
    const uint32_t xorA = (uint32_t)((lane & 7) << 4);
    const int rB0 = warp_n * 128 + matv * 8 + (lane & 7);
    const uint32_t xorB = (uint32_t)((lane & 3) << 4);

    auto wload = [&](const __nv_bfloat16* Wh, const __nv_bfloat16* Wl, int wc) {
        uint32_t st = sb + SM_RW + (uint32_t)(wc & 1) * 32768u;
        #pragma unroll
        for (int u = tid; u < 1024; u += 256) {
            int n = u >> 2, seg = u & 3;
            uint32_t off = (uint32_t)(n * 64) + (((uint32_t)seg * 16) ^ ((uint32_t)(n & 3) << 4));
            size_t go = (size_t)n * 256 + (size_t)wc * 32 + seg * 8;
            cpasync16(st + off,           Wh + go);
            cpasync16(st + 16384u + off,  Wl + go);
        }
        asm volatile("cp.async.commit_group;" ::: "memory");
    };

    auto run_gemm = [&](const __nv_bfloat16* Wh, const __nv_bfloat16* Wl) {
        #pragma unroll
        for (int m = 0; m < 2; ++m)
            #pragma unroll
            for (int j = 0; j < 16; ++j)
                #pragma unroll
                for (int q = 0; q < 4; ++q) acc[m][j][q] = 0.f;
        wload(Wh, Wl, 0);
        wload(Wh, Wl, 1);
        #pragma unroll 1
        for (int wc = 0; wc < 8; ++wc) {
            if (wc < 7) asm volatile("cp.async.wait_group 1;" ::: "memory");
            else        asm volatile("cp.async.wait_group 0;" ::: "memory");
            __syncthreads();
            const uint32_t wst = sb + SM_RW + (uint32_t)(wc & 1) * 32768u;
            #pragma unroll
            for (int ks2 = 0; ks2 < 2; ++ks2) {
                const int K = wc * 2 + ks2;
                const int ac = K >> 2, aks = K & 3;
                const uint32_t abase = sb + SM_RA + (uint32_t)ac * 16384u;
                const uint32_t aco = ((uint32_t)(aks * 32 + kAoff)) ^ xorA;
                uint32_t ah_f[2][4], al_f[2][4];
                #pragma unroll
                for (int mt = 0; mt < 2; ++mt) {
                    uint32_t ro = (uint32_t)((rA0 + mt * 16) * 128);
                    ldsm4(ah_f[mt], abase + ro + aco);
                    ldsm4(al_f[mt], abase + 65536u + ro + aco);
                }
                const uint32_t c0 = ((uint32_t)(ks2 * 32)) ^ xorB;
                const uint32_t c1 = ((uint32_t)(ks2 * 32 + 16)) ^ xorB;
                #pragma unroll
                for (int jb = 0; jb < 4; ++jb) {
                    uint32_t ro = (uint32_t)((rB0 + jb * 32) * 64);
                    uint32_t bh0[4], bh1[4], bl0[4], bl1[4];
                    ldsm4(bh0, wst + ro + c0);
                    ldsm4(bh1, wst + ro + c1);
                    ldsm4(bl0, wst + 16384u + ro + c0);
                    ldsm4(bl1, wst + 16384u + ro + c1);
                    #pragma unroll
                    for (int mt = 0; mt < 2; ++mt)
                        #pragma unroll
                        for (int jj = 0; jj < 4; ++jj) {
                            int j = jb * 4 + jj;
                            mma_bf16(acc[mt][j], ah_f[mt], bh0[jj], bh1[jj]);
                            mma_bf16(acc[mt][j], ah_f[mt], bl0[jj], bl1[jj]);
                            mma_bf16(acc[mt][j], al_f[mt], bh0[jj], bh1[jj]);
                        }
                }
            }
            __syncthreads();
            if (wc + 2 < 8) wload(Wh, Wl, wc + 2);
        }
    };

    // ---------------- GEMM1: u1 = y1 @ W1 ----------------
    run_gemm(W1h, W1l);

    // ---------------- Phase B: h1 = relu(u1+b1) -> bf16 split into RA ----------------
    {
        const float* b1s = (const float*)(smem + SM_B1);
        const int g = lane >> 2, cq = (lane & 3) * 2;
        #pragma unroll
        for (int mt = 0; mt < 2; ++mt) {
            int r = warp_m * 32 + mt * 16 + g;
            #pragma unroll
            for (int j = 0; j < 16; ++j) {
                int col = warp_n * 128 + j * 8 + cq;
                float bb0 = b1s[col], bb1 = b1s[col + 1];
                uint32_t chunk = (uint32_t)(col >> 6);
                uint32_t B = (uint32_t)((col & 63) * 2);
                #pragma unroll
                for (int half = 0; half < 2; ++half) {
                    int rr = r + half * 8;
                    float v0 = fmaxf(acc[mt][j][half * 2]     + bb0, 0.f);
                    float v1 = fmaxf(acc[mt][j][half * 2 + 1] + bb1, 0.f);
                    __nv_bfloat16 h0 = __float2bfloat16_rn(v0), h1 = __float2bfloat16_rn(v1);
                    __nv_bfloat162 hv; hv.x = h0; hv.y = h1;
                    __nv_bfloat162 lv;
                    lv.x = __float2bfloat16_rn(v0 - __bfloat162float(h0));
                    lv.y = __float2bfloat16_rn(v1 - __bfloat162float(h1));
                    uint32_t off = chunk * 16384u + (uint32_t)(rr * 128)
                                 + (B ^ ((uint32_t)(rr & 7) << 4));
                    *(__nv_bfloat162*)(smem + SM_RA + off)          = hv;
                    *(__nv_bfloat162*)(smem + SM_RA + 65536u + off) = lv;
                }
            }
        }
    }
    __syncthreads();

    // ---------------- GEMM2: u2 = h1 @ W2 ----------------
    run_gemm(W2h, W2l);

    // ---------------- Phase D: u2 -> smem fp32; g2 = adj@u2; fused tail ----------------
    {
        float* u2 = (float*)(smem + SM_RA);
        const int g = lane >> 2, cq = (lane & 3) * 2;
        #pragma unroll
        for (int mt = 0; mt < 2; ++mt) {
            int r = warp_m * 32 + mt * 16 + g;
            #pragma unroll
            for (int j = 0; j < 16; ++j) {
                int col = warp_n * 128 + j * 8 + cq;
                *(float2*)(u2 + (size_t)r * 256 + col)       = make_float2(acc[mt][j][0], acc[mt][j][1]);
                *(float2*)(u2 + (size_t)(r + 8) * 256 + col) = make_float2(acc[mt][j][2], acc[mt][j][3]);
            }
        }
    }
    __syncthreads();
    {
        const int b = tid >> 6, t2 = tid & 63;
        const float* u2 = (const float*)(smem + SM_RA);
        float4 uk[30];
        #pragma unroll
        for (int k = 0; k < 30; ++k)
            uk[k] = *(const float4*)(u2 + (size_t)(b * 30 + k) * 256 + t2 * 4);
        float b2v[4], wlv[4];
        #pragma unroll
        for (int q = 0; q < 4; ++q) {
            b2v[q] = __ldg(b2g + t2 * 4 + q);
            wlv[q] = __ldg(wling + t2 * 4 + q);
        }
        const float* ar = adj_s + b * 960;
        float* red = (float*)(smem + SM_RED);
        #pragma unroll 1
        for (int i = 0; i < 30; ++i) {
            float sx = 0.f, sy = 0.f, sz = 0.f, sw = 0.f;
            #pragma unroll
            for (int k = 0; k < 30; ++k) {
                float a = ar[i * 32 + k];
                sx = fmaf(a, uk[k].x, sx);
                sy = fmaf(a, uk[k].y, sy);
                sz = fmaf(a, uk[k].z, sz);
                sw = fmaf(a, uk[k].w, sw);
            }
            float p = fmaxf(sx + b2v[0], 0.f) * wlv[0]
                    + fmaxf(sy + b2v[1], 0.f) * wlv[1]
                    + fmaxf(sz + b2v[2], 0.f) * wlv[2]
                    + fmaxf(sw + b2v[3], 0.f) * wlv[3];
            #pragma unroll
            for (int o = 16; o > 0; o >>= 1) p += __shfl_xor_sync(0xffffffffu, p, o);
            if ((t2 & 31) == 0) red[(b * 30 + i) * 2 + (t2 >> 5)] = p;
        }
    }
    __syncthreads();
    if (tid < 36) {
        const int b = tid / 9, c = tid - b * 9;
        const float* red = (const float*)(smem + SM_RED);
        const float bl = __ldg(bling);
        float s = __ldg(bheadg + c);
        #pragma unroll
        for (int i = 0; i < 30; ++i) {
            float xl = fmaxf(red[(b * 30 + i) * 2] + red[(b * 30 + i) * 2 + 1] + bl, 0.f);
            s = fmaf(xl, __ldg(Wheadg + c * 30 + i), s);
        }
        out[(b0 + b) * 9 + c] = s;
    }
}

// =====================================================================
extern "C" void kernel_launch(void* const* d_in, const int* in_sizes, int n_in,
                              void* d_out, int out_size) {
    const float* real  = (const float*)d_in[0];
    const float* graph = (const float*)d_in[2];
    const float* W1    = (const float*)d_in[3];
    const float* b1    = (const float*)d_in[4];
    const float* W2    = (const float*)d_in[5];
    const float* b2    = (const float*)d_in[6];
    const float* wlin  = (const float*)d_in[7];
    const float* blin  = (const float*)d_in[8];
    const float* Whead = (const float*)d_in[9];
    const float* bhead = (const float*)d_in[10];
    float* out = (float*)d_out;

    __nv_bfloat16 *w1h_p, *w1l_p, *w2h_p, *w2l_p;
    cudaGetSymbolAddress((void**)&w1h_p, g_w1h);
    cudaGetSymbolAddress((void**)&w1l_p, g_w1l);
    cudaGetSymbolAddress((void**)&w2h_p, g_w2h);
    cudaGetSymbolAddress((void**)&w2l_p, g_w2l);

    cudaFuncSetAttribute(mega, cudaFuncAttributeMaxDynamicSharedMemorySize, SMEM_TOTAL);

    prep_w<<<256, 256>>>(W1, W2, w1h_p, w1l_p, w2h_p, w2l_p);
    mega<<<BATCH / 4, 256, SMEM_TOTAL>>>(real, graph, b1, b2, wlin, blin, Whead, bhead,
                                         w1h_p, w1l_p, w2h_p, w2l_p, out);
}

// round 5
// speedup vs baseline: 1.0023x; 1.0023x over previous
#include <cuda_runtime.h>
#include <cuda_bf16.h>
#include <cstdint>

// ---------------- problem constants ----------------
#define BATCH 8192
#define NNODE 30
#define FEAT  256
#define MROWS (BATCH * NNODE)

// ---------------- weights scratch (device globals) ----------------
__device__ __nv_bfloat16 g_w1h[FEAT * FEAT], g_w1l[FEAT * FEAT];
__device__ __nv_bfloat16 g_w2h[FEAT * FEAT], g_w2l[FEAT * FEAT];

// ==================== helpers ====================
__device__ __forceinline__ uint32_t smem_to_u32(const void* p) {
    uint32_t a;
    asm("{ .reg .u64 t; cvta.to.shared.u64 t, %1; cvt.u32.u64 %0, t; }" : "=r"(a) : "l"(p));
    return a;
}
__device__ __forceinline__ void cpasync16(uint32_t saddr, const void* g) {
    asm volatile("cp.async.cg.shared.global [%0], [%1], 16;" :: "r"(saddr), "l"(g));
}
__device__ __forceinline__ void ldsm4(uint32_t* r, uint32_t addr) {
    asm volatile("ldmatrix.sync.aligned.m8n8.x4.shared.b16 {%0,%1,%2,%3}, [%4];"
        : "=r"(r[0]), "=r"(r[1]), "=r"(r[2]), "=r"(r[3]) : "r"(addr));
}
__device__ __forceinline__ void mma_bf16(float* d, const uint32_t* a, uint32_t b0, uint32_t b1) {
    asm volatile(
        "mma.sync.aligned.m16n8k16.row.col.f32.bf16.bf16.f32 "
        "{%0,%1,%2,%3}, {%4,%5,%6,%7}, {%8,%9}, {%0,%1,%2,%3};"
        : "+f"(d[0]), "+f"(d[1]), "+f"(d[2]), "+f"(d[3])
        : "r"(a[0]), "r"(a[1]), "r"(a[2]), "r"(a[3]), "r"(b0), "r"(b1));
}

// =====================================================================
// prep_w: transpose W1/W2 to [N,K] K-major, split into bf16 hi/lo
// =====================================================================
__global__ void prep_w(const float* __restrict__ W1, const float* __restrict__ W2,
                       __nv_bfloat16* __restrict__ w1h, __nv_bfloat16* __restrict__ w1l,
                       __nv_bfloat16* __restrict__ w2h, __nv_bfloat16* __restrict__ w2l) {
    const int n = blockIdx.x, k = threadIdx.x;
    float v1 = W1[k * 256 + n];
    __nv_bfloat16 h1 = __float2bfloat16_rn(v1);
    w1h[n * 256 + k] = h1;
    w1l[n * 256 + k] = __float2bfloat16_rn(v1 - __bfloat162float(h1));
    float v2 = W2[k * 256 + n];
    __nv_bfloat16 h2 = __float2bfloat16_rn(v2);
    w2h[n * 256 + k] = h2;
    w2l[n * 256 + k] = __float2bfloat16_rn(v2 - __bfloat162float(h2));
}

// =====================================================================
// MEGA kernel: 4 batches (120 rows, padded to 128) per CTA, 256 threads.
// smem layout:
//   RA   [0,       131072): A region. Phases: y1split -> h1split -> u2(fp32)
//        split layout: hi = 4 chunks of [128 x 64]bf16 (16KB, SW128-swizzled)
//                      lo = same at +65536
//   RW   [131072,  196608): W stages (2 x 32KB: hi 16KB + lo 16KB, KC=32)
//                           (phase A: x stages 2 x 30720B)
//   ADJ  [196608,  211968): adj 4 x [30 x 32] fp32
//   B1   [211968,  212992): bias1 256 fp32
//   RED  [212992,  213952): reduction scratch 4*30*2 fp32
// =====================================================================
#define SM_RA   0u
#define SM_RW   131072u
#define SM_ADJ  196608u
#define SM_B1   211968u
#define SM_RED  212992u
#define SMEM_TOTAL 214016

__global__ __launch_bounds__(256, 1)
void mega(const float* __restrict__ x, const float* __restrict__ graph,
          const float* __restrict__ b1g, const float* __restrict__ b2g,
          const float* __restrict__ wling, const float* __restrict__ bling,
          const float* __restrict__ Wheadg, const float* __restrict__ bheadg,
          const __nv_bfloat16* __restrict__ W1h, const __nv_bfloat16* __restrict__ W1l,
          const __nv_bfloat16* __restrict__ W2h, const __nv_bfloat16* __restrict__ W2l,
          float* __restrict__ out) {
    extern __shared__ char smem[];
    const uint32_t sb = smem_to_u32(smem);
    const int tid = threadIdx.x, lane = tid & 31, wid = tid >> 5;
    const int warp_m = wid & 3, warp_n = wid >> 2;
    const size_t b0 = (size_t)blockIdx.x * 4;
    float* adj_s = (float*)(smem + SM_ADJ);

    // ---------------- adj = mean(graph, bands) ----------------
    for (int e = tid; e < 3600; e += 256) {
        int b = e / 900, i = e - b * 900;
        const float* gp = graph + (b0 + b) * 4500 + i;
        float s = 0.2f * (gp[0] + gp[900] + gp[1800] + gp[2700] + gp[3600]);
        adj_s[b * 960 + (i / 30) * 32 + (i % 30)] = s;
    }
    ((float*)(smem + SM_B1))[tid] = b1g[tid];

    // ---------------- Phase A: y1 = adj @ x -> bf16 split ----------------
    auto xload = [&](int c) {
        const float* gx = x + (b0 * 30) * 256 + c * 64;
        uint32_t st = sb + SM_RW + (uint32_t)(c & 1) * 30720u;
        #pragma unroll
        for (int u = tid; u < 1920; u += 256) {
            int row = u >> 4, seg = u & 15;
            cpasync16(st + (uint32_t)(row * 256 + seg * 16), gx + (size_t)row * 256 + seg * 4);
        }
        asm volatile("cp.async.commit_group;" ::: "memory");
    };
    xload(0);
    xload(1);

    const int pb = tid >> 6, phalf = (tid >> 5) & 1, pcp = tid & 31;
    __syncthreads();   // adj + b1 visible

    #pragma unroll 1
    for (int c = 0; c < 4; ++c) {
        if (c < 3) asm volatile("cp.async.wait_group 1;" ::: "memory");
        else       asm volatile("cp.async.wait_group 0;" ::: "memory");
        __syncthreads();
        const float* xs = (const float*)(smem + SM_RW + (c & 1) * 30720);
        float2 xk[30];
        #pragma unroll
        for (int k = 0; k < 30; ++k)
            xk[k] = *(const float2*)(xs + (pb * 30 + k) * 64 + pcp * 2);
        const float* ar = adj_s + pb * 960 + phalf * 15 * 32;
        #pragma unroll 1
        for (int i = 0; i < 15; ++i) {
            float s0 = 0.f, s1 = 0.f;
            #pragma unroll
            for (int k = 0; k < 30; ++k) {
                float a = ar[i * 32 + k];
                s0 = fmaf(a, xk[k].x, s0);
                s1 = fmaf(a, xk[k].y, s1);
            }
            int r = pb * 30 + phalf * 15 + i;
            __nv_bfloat16 h0 = __float2bfloat16_rn(s0), h1 = __float2bfloat16_rn(s1);
            __nv_bfloat162 hv; hv.x = h0; hv.y = h1;
            __nv_bfloat162 lv;
            lv.x = __float2bfloat16_rn(s0 - __bfloat162float(h0));
            lv.y = __float2bfloat16_rn(s1 - __bfloat162float(h1));
            uint32_t B = (uint32_t)(pcp * 4);
            uint32_t off = (uint32_t)c * 16384u + (uint32_t)(r * 128)
                         + (B ^ ((uint32_t)(r & 7) << 4));
            *(__nv_bfloat162*)(smem + SM_RA + off)           = hv;
            *(__nv_bfloat162*)(smem + SM_RA + 65536u + off)  = lv;
        }
        // zero pad rows 120..127 (hi and lo)
        if (tid < 128) {
            int hl = tid >> 6, rr = 120 + ((tid >> 3) & 7), seg = tid & 7;
            uint32_t off = (uint32_t)c * 16384u + (uint32_t)(rr * 128 + seg * 16)
                         + (uint32_t)hl * 65536u;
            *(uint4*)(smem + SM_RA + off) = make_uint4(0, 0, 0, 0);
        }
        __syncthreads();
        if (c + 2 < 4) xload(c + 2);
    }

    // ---------------- GEMM machinery ----------------
    float acc[2][16][4];
    const int matv = lane >> 3;
    const int rA0 = warp_m * 32 + (matv & 1) * 8 + (lane & 7);
    const int kAoff = (matv >> 1) * 16;
    const uint32_t xorA = (uint32_t)((lane & 7) << 4);
    const int rB0 = warp_n * 128 + matv * 8 + (lane & 7);
    const uint32_t xorB = (uint32_t)((lane & 3) << 4);

    auto wload = [&](const __nv_bfloat16* Wh, const __nv_bfloat16* Wl, int wc) {
        uint32_t st = sb + SM_RW + (uint32_t)(wc & 1) * 32768u;
        #pragma unroll
        for (int u = tid; u < 1024; u += 256) {
            int n = u >> 2, seg = u & 3;
            uint32_t off = (uint32_t)(n * 64) + (((uint32_t)seg * 16) ^ ((uint32_t)(n & 3) << 4));
            size_t go = (size_t)n * 256 + (size_t)wc * 32 + seg * 8;
            cpasync16(st + off,           Wh + go);
            cpasync16(st + 16384u + off,  Wl + go);
        }
        asm volatile("cp.async.commit_group;" ::: "memory");
    };

    auto run_gemm = [&](const __nv_bfloat16* Wh, const __nv_bfloat16* Wl) {
        #pragma unroll
        for (int m = 0; m < 2; ++m)
            #pragma unroll
            for (int j = 0; j < 16; ++j)
                #pragma unroll
                for (int q = 0; q < 4; ++q) acc[m][j][q] = 0.f;
        wload(Wh, Wl, 0);
        wload(Wh, Wl, 1);
        #pragma unroll 1
        for (int wc = 0; wc < 8; ++wc) {
            if (wc < 7) asm volatile("cp.async.wait_group 1;" ::: "memory");
            else        asm volatile("cp.async.wait_group 0;" ::: "memory");
            __syncthreads();
            const uint32_t wst = sb + SM_RW + (uint32_t)(wc & 1) * 32768u;
            #pragma unroll
            for (int ks2 = 0; ks2 < 2; ++ks2) {
                const int K = wc * 2 + ks2;
                const int ac = K >> 2, aks = K & 3;
                const uint32_t abase = sb + SM_RA + (uint32_t)ac * 16384u;
                const uint32_t aco = ((uint32_t)(aks * 32 + kAoff)) ^ xorA;
                uint32_t ah_f[2][4], al_f[2][4];
                #pragma unroll
                for (int mt = 0; mt < 2; ++mt) {
                    uint32_t ro = (uint32_t)((rA0 + mt * 16) * 128);
                    ldsm4(ah_f[mt], abase + ro + aco);
                    ldsm4(al_f[mt], abase + 65536u + ro + aco);
                }
                const uint32_t c0 = ((uint32_t)(ks2 * 32)) ^ xorB;
                const uint32_t c1 = ((uint32_t)(ks2 * 32 + 16)) ^ xorB;
                #pragma unroll
                for (int jb = 0; jb < 4; ++jb) {
                    uint32_t ro = (uint32_t)((rB0 + jb * 32) * 64);
                    uint32_t bh0[4], bh1[4], bl0[4], bl1[4];
                    ldsm4(bh0, wst + ro + c0);
                    ldsm4(bh1, wst + ro + c1);
                    ldsm4(bl0, wst + 16384u + ro + c0);
                    ldsm4(bl1, wst + 16384u + ro + c1);
                    #pragma unroll
                    for (int mt = 0; mt < 2; ++mt)
                        #pragma unroll
                        for (int jj = 0; jj < 4; ++jj) {
                            int j = jb * 4 + jj;
                            mma_bf16(acc[mt][j], ah_f[mt], bh0[jj], bh1[jj]);
                            mma_bf16(acc[mt][j], ah_f[mt], bl0[jj], bl1[jj]);
                            mma_bf16(acc[mt][j], al_f[mt], bh0[jj], bh1[jj]);
                        }
                }
            }
            __syncthreads();
            if (wc + 2 < 8) wload(Wh, Wl, wc + 2);
        }
    };

    // ---------------- GEMM1: u1 = y1 @ W1 ----------------
    run_gemm(W1h, W1l);

    // ---------------- Phase B: h1 = relu(u1+b1) -> bf16 split into RA ----------------
    {
        const float* b1s = (const float*)(smem + SM_B1);
        const int g = lane >> 2, cq = (lane & 3) * 2;
        #pragma unroll
        for (int mt = 0; mt < 2; ++mt) {
            int r = warp_m * 32 + mt * 16 + g;
            #pragma unroll
            for (int j = 0; j < 16; ++j) {
                int col = warp_n * 128 + j * 8 + cq;
                float bb0 = b1s[col], bb1 = b1s[col + 1];
                uint32_t chunk = (uint32_t)(col >> 6);
                uint32_t B = (uint32_t)((col & 63) * 2);
                #pragma unroll
                for (int half = 0; half < 2; ++half) {
                    int rr = r + half * 8;
                    float v0 = fmaxf(acc[mt][j][half * 2]     + bb0, 0.f);
                    float v1 = fmaxf(acc[mt][j][half * 2 + 1] + bb1, 0.f);
                    __nv_bfloat16 h0 = __float2bfloat16_rn(v0), h1 = __float2bfloat16_rn(v1);
                    __nv_bfloat162 hv; hv.x = h0; hv.y = h1;
                    __nv_bfloat162 lv;
                    lv.x = __float2bfloat16_rn(v0 - __bfloat162float(h0));
                    lv.y = __float2bfloat16_rn(v1 - __bfloat162float(h1));
                    uint32_t off = chunk * 16384u + (uint32_t)(rr * 128)
                                 + (B ^ ((uint32_t)(rr & 7) << 4));
                    *(__nv_bfloat162*)(smem + SM_RA + off)          = hv;
                    *(__nv_bfloat162*)(smem + SM_RA + 65536u + off) = lv;
                }
            }
        }
    }
    __syncthreads();

    // ---------------- GEMM2: u2 = h1 @ W2 ----------------
    run_gemm(W2h, W2l);

    // ---------------- Phase D: u2 -> smem fp32; g2 = adj@u2; fused tail ----------------
    {
        float* u2 = (float*)(smem + SM_RA);
        const int g = lane >> 2, cq = (lane & 3) * 2;
        #pragma unroll
        for (int mt = 0; mt < 2; ++mt) {
            int r = warp_m * 32 + mt * 16 + g;
            #pragma unroll
            for (int j = 0; j < 16; ++j) {
                int col = warp_n * 128 + j * 8 + cq;
                *(float2*)(u2 + (size_t)r * 256 + col)       = make_float2(acc[mt][j][0], acc[mt][j][1]);
                *(float2*)(u2 + (size_t)(r + 8) * 256 + col) = make_float2(acc[mt][j][2], acc[mt][j][3]);
            }
        }
    }
    __syncthreads();
    {
        const int b = tid >> 6, t2 = tid & 63;
        const float* u2 = (const float*)(smem + SM_RA);
        float4 uk[30];
        #pragma unroll
        for (int k = 0; k < 30; ++k)
            uk[k] = *(const float4*)(u2 + (size_t)(b * 30 + k) * 256 + t2 * 4);
        float b2v[4], wlv[4];
        #pragma unroll
        for (int q = 0; q < 4; ++q) {
            b2v[q] = __ldg(b2g + t2 * 4 + q);
            wlv[q] = __ldg(wling + t2 * 4 + q);
        }
        const float* ar = adj_s + b * 960;
        float* red = (float*)(smem + SM_RED);
        #pragma unroll 1
        for (int i = 0; i < 30; ++i) {
            float sx = 0.f, sy = 0.f, sz = 0.f, sw = 0.f;
            #pragma unroll
            for (int k = 0; k < 30; ++k) {
                float a = ar[i * 32 + k];
                sx = fmaf(a, uk[k].x, sx);
                sy = fmaf(a, uk[k].y, sy);
                sz = fmaf(a, uk[k].z, sz);
                sw = fmaf(a, uk[k].w, sw);
            }
            float p = fmaxf(sx + b2v[0], 0.f) * wlv[0]
                    + fmaxf(sy + b2v[1], 0.f) * wlv[1]
                    + fmaxf(sz + b2v[2], 0.f) * wlv[2]
                    + fmaxf(sw + b2v[3], 0.f) * wlv[3];
            #pragma unroll
            for (int o = 16; o > 0; o >>= 1) p += __shfl_xor_sync(0xffffffffu, p, o);
            if ((t2 & 31) == 0) red[(b * 30 + i) * 2 + (t2 >> 5)] = p;
        }
    }
    __syncthreads();
    if (tid < 36) {
        const int b = tid / 9, c = tid - b * 9;
        const float* red = (const float*)(smem + SM_RED);
        const float bl = __ldg(bling);
        float s = __ldg(bheadg + c);
        #pragma unroll
        for (int i = 0; i < 30; ++i) {
            float xl = fmaxf(red[(b * 30 + i) * 2] + red[(b * 30 + i) * 2 + 1] + bl, 0.f);
            s = fmaf(xl, __ldg(Wheadg + c * 30 + i), s);
        }
        out[(b0 + b) * 9 + c] = s;
    }
}

// =====================================================================
extern "C" void kernel_launch(void* const* d_in, const int* in_sizes, int n_in,
                              void* d_out, int out_size) {
    const float* real  = (const float*)d_in[0];
    const float* graph = (const float*)d_in[2];
    const float* W1    = (const float*)d_in[3];
    const float* b1    = (const float*)d_in[4];
    const float* W2    = (const float*)d_in[5];
    const float* b2    = (const float*)d_in[6];
    const float* wlin  = (const float*)d_in[7];
    const float* blin  = (const float*)d_in[8];
    const float* Whead = (const float*)d_in[9];
    const float* bhead = (const float*)d_in[10];
    float* out = (float*)d_out;

    __nv_bfloat16 *w1h_p, *w1l_p, *w2h_p, *w2l_p;
    cudaGetSymbolAddress((void**)&w1h_p, g_w1h);
    cudaGetSymbolAddress((void**)&w1l_p, g_w1l);
    cudaGetSymbolAddress((void**)&w2h_p, g_w2h);
    cudaGetSymbolAddress((void**)&w2l_p, g_w2l);

    cudaFuncSetAttribute(mega, cudaFuncAttributeMaxDynamicSharedMemorySize, SMEM_TOTAL);

    prep_w<<<256, 256>>>(W1, W2, w1h_p, w1l_p, w2h_p, w2l_p);
    mega<<<BATCH / 4, 256, SMEM_TOTAL>>>(real, graph, b1, b2, wlin, blin, Whead, bhead,
                                         w1h_p, w1l_p, w2h_p, w2l_p, out);
}